// round 16
// baseline (speedup 1.0000x reference)
#include <cuda_runtime.h>
#include <cuda_fp16.h>
#include <math.h>

#define BB 2
#define NS 2048
#define DD 1024
#define HH 16
#define DHH 64
#define INNERD 1024
#define LNEPS 1e-5f

// ------------------------- scratch -------------------------
__device__ __align__(16) __half g_xnh[BB * NS * DD];
__device__ __align__(16) __half g_qh[BB * NS * INNERD];
__device__ __align__(16) __half g_kh[BB * NS * DHH];
__device__ __align__(16) __half g_vhT[BB * DHH * NS];
__device__ __align__(16) __half g_ctxh[BB * NS * INNERD];
__device__ __align__(16) __half g_wqT[INNERD * DD];
__device__ __align__(16) __half g_woT[DD * INNERD];
__device__ float g_mkf[BB * NS];

// ------------------------- helpers -------------------------
__device__ __forceinline__ unsigned f2tf32(float f) {
    unsigned u; asm("cvt.rna.tf32.f32 %0, %1;" : "=r"(u) : "f"(f)); return u;
}
__device__ __forceinline__ void mma8(float* c, const unsigned* a, const unsigned* b) {
    asm volatile(
        "mma.sync.aligned.m16n8k8.row.col.f32.tf32.tf32.f32 "
        "{%0,%1,%2,%3}, {%4,%5,%6,%7}, {%8,%9}, {%0,%1,%2,%3};\n"
        : "+f"(c[0]), "+f"(c[1]), "+f"(c[2]), "+f"(c[3])
        : "r"(a[0]), "r"(a[1]), "r"(a[2]), "r"(a[3]), "r"(b[0]), "r"(b[1]));
}
__device__ __forceinline__ void mma16h(float* c, const unsigned* a, const unsigned* b) {
    asm volatile(
        "mma.sync.aligned.m16n8k16.row.col.f32.f16.f16.f32 "
        "{%0,%1,%2,%3}, {%4,%5,%6,%7}, {%8,%9}, {%0,%1,%2,%3};\n"
        : "+f"(c[0]), "+f"(c[1]), "+f"(c[2]), "+f"(c[3])
        : "r"(a[0]), "r"(a[1]), "r"(a[2]), "r"(a[3]), "r"(b[0]), "r"(b[1]));
}
__device__ __forceinline__ unsigned packh2(float lo, float hi) {
    unsigned r; asm("cvt.rn.f16x2.f32 %0, %1, %2;" : "=r"(r) : "f"(hi), "f"(lo)); return r;
}
__device__ __forceinline__ void cp16(void* dst_smem, const void* src) {
    unsigned d = (unsigned)__cvta_generic_to_shared(dst_smem);
    asm volatile("cp.async.cg.shared.global [%0], [%1], 16;\n" :: "r"(d), "l"(src));
}
__device__ __forceinline__ void cp_commit() { asm volatile("cp.async.commit_group;" ::: "memory"); }
__device__ __forceinline__ void cp_wait1() { asm volatile("cp.async.wait_group 1;" ::: "memory"); }
__device__ __forceinline__ void cp_wait0() { asm volatile("cp.async.wait_group 0;" ::: "memory"); }

// ------------------------- mask: detect dtype + expand -------------------------
__global__ void mask_kernel(const unsigned char* __restrict__ m) {
    __shared__ int cnt;
    int tid = threadIdx.x;
    if (tid == 0) cnt = 0;
    __syncthreads();
    int c = 0;
    for (int i = tid; i < 4096; i += 256) c += (m[i] != 0);
    atomicAdd(&cnt, c);
    __syncthreads();
    bool m4 = (cnt <= 2048);
    for (int i = tid; i < BB * NS; i += 256) {
        bool v = m4 ? (((const unsigned*)m)[i] != 0u) : (m[i] != 0);
        g_mkf[i] = v ? 1.f : 0.f;
    }
}

// ------------------------- LayerNorm (fp16 out) -------------------------
__global__ void ln_kernel(const float* __restrict__ x,
                          const float* __restrict__ w,
                          const float* __restrict__ b) {
    int row = blockIdx.x;
    const float* xr = x + (size_t)row * DD;
    int i4 = threadIdx.x * 4;
    float4 v = *(const float4*)&xr[i4];
    float s  = v.x + v.y + v.z + v.w;
    float s2 = v.x * v.x + v.y * v.y + v.z * v.z + v.w * v.w;
#pragma unroll
    for (int o = 16; o; o >>= 1) {
        s  += __shfl_xor_sync(0xffffffffu, s,  o);
        s2 += __shfl_xor_sync(0xffffffffu, s2, o);
    }
    __shared__ float as_[8], bs_[8];
    __shared__ float mu_s, inv_s;
    int wid = threadIdx.x >> 5, lane = threadIdx.x & 31;
    if (lane == 0) { as_[wid] = s; bs_[wid] = s2; }
    __syncthreads();
    if (threadIdx.x == 0) {
        float ts = 0.f, ts2 = 0.f;
#pragma unroll
        for (int k = 0; k < 8; k++) { ts += as_[k]; ts2 += bs_[k]; }
        float mu  = ts * (1.f / DD);
        float var = ts2 * (1.f / DD) - mu * mu;
        mu_s = mu;
        inv_s = rsqrtf(var + LNEPS);
    }
    __syncthreads();
    float mu = mu_s, inv = inv_s;
    float4 wv = *(const float4*)&w[i4];
    float4 bv = *(const float4*)&b[i4];
    float rx = (v.x - mu) * inv * wv.x + bv.x;
    float ry = (v.y - mu) * inv * wv.y + bv.y;
    float rz = (v.z - mu) * inv * wv.z + bv.z;
    float rw = (v.w - mu) * inv * wv.w + bv.w;
    __half2* d = (__half2*)&g_xnh[(size_t)row * DD + i4];
    d[0] = __floats2half2_rn(rx, ry);
    d[1] = __floats2half2_rn(rz, rw);
}

// ------------------------- weight transpose+convert -------------------------
__global__ void transp_kernel(const float* __restrict__ wq, const float* __restrict__ wo) {
    const float* in = blockIdx.z ? wo : wq;
    __half* out = blockIdx.z ? g_woT : g_wqT;
    const int R = 1024, C = 1024;
    __shared__ float t[32][33];
    int c0 = blockIdx.x * 32, r0 = blockIdx.y * 32;
    int tx = threadIdx.x & 31, ty = threadIdx.x >> 5;
#pragma unroll
    for (int i = ty; i < 32; i += 8)
        t[i][tx] = in[(size_t)(r0 + i) * C + c0 + tx];
    __syncthreads();
#pragma unroll
    for (int i = ty; i < 32; i += 8)
        out[(size_t)(c0 + i) * R + r0 + tx] = __float2half(t[tx][i]);
}

// ------------------------- tf32 kv GEMM + fused K/V^T epilogue -------------------------
#define GAS 20
#define GWS 72

__global__ __launch_bounds__(256) void gemm_kv_kernel(
        const float* __restrict__ A, const float* __restrict__ W) {
    const int K = DD, N = 2 * DHH;
    __shared__ float As[3][128 * GAS];
    __shared__ float Ws[3][16 * GWS];

    int tid = threadIdx.x, lane = tid & 31, w = tid >> 5;
    int g = lane >> 2, c = lane & 3;
    int wm = (w & 3) * 32, wn = (w >> 2) * 32;
    int bm = blockIdx.y * 128, bn = blockIdx.x * 64;
    int ar = tid >> 2, ac = (tid & 3) * 4;
    int wr = tid >> 4, wc = (tid & 15) * 4;

    const int nIter = K / 16;
    float acc[2][4][4] = {};

#pragma unroll
    for (int p = 0; p < 2; p++) {
        int k0 = p * 16;
        cp16(&As[p][ar * GAS + ac], &A[(size_t)(bm + ar) * K + k0 + ac]);
        cp16(&As[p][(ar + 64) * GAS + ac], &A[(size_t)(bm + ar + 64) * K + k0 + ac]);
        cp16(&Ws[p][wr * GWS + wc], &W[(size_t)(k0 + wr) * N + bn + wc]);
        cp_commit();
    }
    for (int i = 0; i < nIter; i++) {
        if (i == nIter - 1) cp_wait0(); else cp_wait1();
        __syncthreads();
        if (i + 2 < nIter) {
            int s = (i + 2) % 3, k0 = (i + 2) * 16;
            cp16(&As[s][ar * GAS + ac], &A[(size_t)(bm + ar) * K + k0 + ac]);
            cp16(&As[s][(ar + 64) * GAS + ac], &A[(size_t)(bm + ar + 64) * K + k0 + ac]);
            cp16(&Ws[s][wr * GWS + wc], &W[(size_t)(k0 + wr) * N + bn + wc]);
            cp_commit();
        }
        const float* as_ = As[i % 3];
        const float* ws_ = Ws[i % 3];
#pragma unroll
        for (int ks = 0; ks < 16; ks += 8) {
            unsigned af[2][4], bf[4][2];
#pragma unroll
            for (int mi = 0; mi < 2; mi++) {
                int r = wm + mi * 16 + g;
                af[mi][0] = f2tf32(as_[r * GAS + ks + c]);
                af[mi][1] = f2tf32(as_[(r + 8) * GAS + ks + c]);
                af[mi][2] = f2tf32(as_[r * GAS + ks + c + 4]);
                af[mi][3] = f2tf32(as_[(r + 8) * GAS + ks + c + 4]);
            }
#pragma unroll
            for (int ni = 0; ni < 4; ni++) {
                bf[ni][0] = f2tf32(ws_[(ks + c) * GWS + wn + ni * 8 + g]);
                bf[ni][1] = f2tf32(ws_[(ks + c + 4) * GWS + wn + ni * 8 + g]);
            }
#pragma unroll
            for (int mi = 0; mi < 2; mi++)
#pragma unroll
                for (int ni = 0; ni < 4; ni++)
                    mma8(acc[mi][ni], af[mi], bf[ni]);
        }
    }

    if (bn == 0) {
#pragma unroll
        for (int mi = 0; mi < 2; mi++)
#pragma unroll
            for (int ni = 0; ni < 4; ni++) {
                int r = bm + wm + mi * 16 + g;
                int cc = wn + ni * 8 + c * 2;
                *(unsigned*)&g_kh[(size_t)r * DHH + cc] = packh2(acc[mi][ni][0], acc[mi][ni][1]);
                *(unsigned*)&g_kh[(size_t)(r + 8) * DHH + cc] = packh2(acc[mi][ni][2], acc[mi][ni][3]);
            }
    } else {
        __syncthreads();
        __half* vt = (__half*)As;
#pragma unroll
        for (int mi = 0; mi < 2; mi++)
#pragma unroll
            for (int ni = 0; ni < 4; ni++) {
                int mr = wm + mi * 16 + g;
                int col = wn + ni * 8 + c * 2;
                *(unsigned*)&vt[mr * 72 + col] = packh2(acc[mi][ni][0], acc[mi][ni][1]);
                *(unsigned*)&vt[(mr + 8) * 72 + col] = packh2(acc[mi][ni][2], acc[mi][ni][3]);
            }
        __syncthreads();
        int d = tid >> 2, ns0 = (tid & 3) * 32;
        int bsel = bm >= NS;
        int n0 = bm - bsel * NS;
        __half tmp[32];
#pragma unroll
        for (int i = 0; i < 32; i++) tmp[i] = vt[(ns0 + i) * 72 + d];
        __half* dst = g_vhT + ((size_t)(bsel * DHH + d)) * NS + n0 + ns0;
#pragma unroll
        for (int i = 0; i < 4; i++)
            *(uint4*)(dst + i * 8) = *(uint4*)&tmp[i * 8];
    }
}

// ------------------------- fp16 GEMM 128x128 (R14) -------------------------
__device__ __forceinline__ const __half* h_a_ptr(int s) { return s == 0 ? g_xnh : g_ctxh; }
__device__ __forceinline__ const __half* h_w_ptr(int s) { return s == 0 ? g_wqT : g_woT; }

#define HST 20
#define GH_AS_WORDS (3 * 128 * HST)
#define GH_SMEM_BYTES ((2 * GH_AS_WORDS) * 4)

__global__ __launch_bounds__(256) void gemm_h_kernel(
        int sel, float* __restrict__ Cext, int K, int N, float scale) {
    const __half* A = h_a_ptr(sel);
    const __half* WT = h_w_ptr(sel);

    extern __shared__ unsigned gsm[];
    unsigned* Asb = gsm;
    unsigned* Wsb = gsm + GH_AS_WORDS;

    int tid = threadIdx.x, lane = tid & 31, w = tid >> 5;
    int g = lane >> 2, c = lane & 3;
    int wm = (w & 3) * 32, wn = (w >> 2) * 64;
    int bm = blockIdx.y * 128, bn = blockIdx.x * 128;
    int row2 = tid >> 1, seg2 = tid & 1;

    const int nIter = K / 32;
    float acc[2][8][4] = {};

    auto stage = [&](int s, int k0) {
        unsigned aw = s * (128 * HST) + row2 * HST + seg2 * 8;
        const __half* asrc = A + (size_t)(bm + row2) * K + k0 + seg2 * 16;
        cp16(&Asb[aw], asrc);
        cp16(&Asb[aw + 4], asrc + 8);
        unsigned ww = s * (128 * HST) + row2 * HST + seg2 * 8;
        const __half* wsrc = WT + (size_t)(bn + row2) * K + k0 + seg2 * 16;
        cp16(&Wsb[ww], wsrc);
        cp16(&Wsb[ww + 4], wsrc + 8);
        cp_commit();
    };

    stage(0, 0);
    stage(1, 32);

    for (int i = 0; i < nIter; i++) {
        if (i == nIter - 1) cp_wait0(); else cp_wait1();
        __syncthreads();
        if (i + 2 < nIter) stage((i + 2) % 3, (i + 2) * 32);
        const unsigned* as_ = Asb + (i % 3) * (128 * HST);
        const unsigned* ws_ = Wsb + (i % 3) * (128 * HST);
#pragma unroll
        for (int ks = 0; ks < 16; ks += 8) {
            unsigned af[2][4], bf[8][2];
#pragma unroll
            for (int mi = 0; mi < 2; mi++) {
                int r = wm + mi * 16 + g;
                af[mi][0] = as_[r * HST + ks + c];
                af[mi][1] = as_[(r + 8) * HST + ks + c];
                af[mi][2] = as_[r * HST + ks + c + 4];
                af[mi][3] = as_[(r + 8) * HST + ks + c + 4];
            }
#pragma unroll
            for (int ni = 0; ni < 8; ni++) {
                int n = wn + ni * 8 + g;
                bf[ni][0] = ws_[n * HST + ks + c];
                bf[ni][1] = ws_[n * HST + ks + c + 4];
            }
#pragma unroll
            for (int mi = 0; mi < 2; mi++)
#pragma unroll
                for (int ni = 0; ni < 8; ni++)
                    mma16h(acc[mi][ni], af[mi], bf[ni]);
        }
    }

#pragma unroll
    for (int mi = 0; mi < 2; mi++)
#pragma unroll
        for (int ni = 0; ni < 8; ni++) {
            int r = bm + wm + mi * 16 + g;
            int cc = bn + wn + ni * 8 + c * 2;
            if (sel == 0) {
                *(unsigned*)&g_qh[(size_t)r * N + cc] = packh2(acc[mi][ni][0] * scale, acc[mi][ni][1] * scale);
                *(unsigned*)&g_qh[(size_t)(r + 8) * N + cc] = packh2(acc[mi][ni][2] * scale, acc[mi][ni][3] * scale);
            } else {
                float2 r0; r0.x = acc[mi][ni][0] * scale; r0.y = acc[mi][ni][1] * scale;
                float2 r1; r1.x = acc[mi][ni][2] * scale; r1.y = acc[mi][ni][3] * scale;
                *(float2*)&Cext[(size_t)r * N + cc] = r0;
                *(float2*)&Cext[(size_t)(r + 8) * N + cc] = r1;
            }
        }
}

// ------------------------- flash attention v7: 64-row CTAs for wave balance -------------------------
// CTA = (b, h, 64 q-rows), 128 threads / 4 warps; warp = 16 rows x 64 keys
// (per-warp code identical to R12). Grid 1024 CTAs @ 6 CTAs/SM (888 slots):
// wave utilization 58% -> ~77% vs the 512-CTA/3-slot configuration.
#define KVW 36
#define VS_OFF   (2 * 64 * KVW)
#define MK_OFF   (4 * 64 * KVW)
#define ATTN_SMEM_FLOATS (MK_OFF + 2 * 64)
#define ATTN_SMEM_BYTES  (ATTN_SMEM_FLOATS * 4)
#define NKT (NS / 64)

__global__ __launch_bounds__(128, 6) void attn_kernel(const float* __restrict__ bias) {
    extern __shared__ float sm[];
    unsigned* ksu = (unsigned*)sm;
    unsigned* vsu = (unsigned*)sm + VS_OFF;

    int tid = threadIdx.x, lane = tid & 31, w = tid >> 5;
    int g = lane >> 2, c = lane & 3;
    int wm = w * 16;                       // warp's 16-row band of 64
    int b = blockIdx.x & 1, qt = blockIdx.x >> 1, h = blockIdx.y;
    int qbase = qt * 64;

    const float* bias_r0 = bias + (size_t)h * NS * NS + (size_t)(qbase + wm + g) * NS;
    const float* bias_r8 = bias_r0 + (size_t)8 * NS;

    auto stage = [&](int kt, int buf) {
        int kbase = kt * 64;
        int r = tid >> 1, seg = tid & 1;   // 2 threads per 128B row, 4 cp16 each
        unsigned* kdst = ksu + buf * (64 * KVW) + r * KVW + seg * 16;
        const __half* ksrc = g_kh + ((size_t)(b * NS + kbase + r)) * DHH + seg * 32;
#pragma unroll
        for (int i = 0; i < 4; i++) cp16(kdst + i * 4, ksrc + i * 8);
        unsigned* vdst = vsu + buf * (64 * KVW) + r * KVW + seg * 16;
        const __half* vsrc = g_vhT + ((size_t)(b * DHH + r)) * NS + kbase + seg * 32;
#pragma unroll
        for (int i = 0; i < 4; i++) cp16(vdst + i * 4, vsrc + i * 8);
        if (tid < 16) cp16(sm + MK_OFF + buf * 64 + tid * 4, g_mkf + b * NS + kbase + tid * 4);
        cp_commit();
    };

    stage(0, 0);

    const unsigned* qu = (const unsigned*)g_qh;
    unsigned qa[4][4];
    {
        size_t rlo = (size_t)(b * NS + qbase + wm + g) * 512 + h * 32;
        size_t rhi = rlo + 8 * 512;
#pragma unroll
        for (int t4 = 0; t4 < 4; t4++) {
            qa[t4][0] = qu[rlo + t4 * 8 + c];
            qa[t4][1] = qu[rhi + t4 * 8 + c];
            qa[t4][2] = qu[rlo + t4 * 8 + c + 4];
            qa[t4][3] = qu[rhi + t4 * 8 + c + 4];
        }
    }

    float o[8][4] = {};
    float l_lo = 0.f, l_hi = 0.f;

    for (int kt = 0; kt < NKT; kt++) {
        __syncthreads();
        if (kt + 1 < NKT) { stage(kt + 1, (kt + 1) & 1); cp_wait1(); }
        else cp_wait0();
        __syncthreads();

        int buf = kt & 1;
        int kbase = kt * 64;
        const unsigned* ksb = ksu + buf * (64 * KVW);
        const unsigned* vsb = vsu + buf * (64 * KVW);
        const float* mkb = sm + MK_OFF + buf * 64;

#pragma unroll
        for (int t = 0; t < 4; t++) {
            float2 bl0 = *(const float2*)&bias_r0[kbase + t * 16 + 2 * c];
            float2 bh0 = *(const float2*)&bias_r8[kbase + t * 16 + 2 * c];
            float2 bl1 = *(const float2*)&bias_r0[kbase + t * 16 + 8 + 2 * c];
            float2 bh1 = *(const float2*)&bias_r8[kbase + t * 16 + 8 + 2 * c];

            float s0[4] = {}, s1[4] = {};
#pragma unroll
            for (int t4 = 0; t4 < 4; t4++) {
                unsigned b0[2], b1[2];
                b0[0] = ksb[(t * 16 + g) * KVW + t4 * 8 + c];
                b0[1] = ksb[(t * 16 + g) * KVW + t4 * 8 + c + 4];
                b1[0] = ksb[(t * 16 + 8 + g) * KVW + t4 * 8 + c];
                b1[1] = ksb[(t * 16 + 8 + g) * KVW + t4 * 8 + c + 4];
                mma16h(s0, qa[t4], b0);
                mma16h(s1, qa[t4], b1);
            }
            float2 mv0 = *(const float2*)&mkb[t * 16 + 2 * c];
            float2 mv1 = *(const float2*)&mkb[t * 16 + 8 + 2 * c];
            float p0 = (mv0.x != 0.f) ? __expf(s0[0] + bl0.x) : 0.f;
            float p1 = (mv0.y != 0.f) ? __expf(s0[1] + bl0.y) : 0.f;
            float p2 = (mv0.x != 0.f) ? __expf(s0[2] + bh0.x) : 0.f;
            float p3 = (mv0.y != 0.f) ? __expf(s0[3] + bh0.y) : 0.f;
            float r0 = (mv1.x != 0.f) ? __expf(s1[0] + bl1.x) : 0.f;
            float r1 = (mv1.y != 0.f) ? __expf(s1[1] + bl1.y) : 0.f;
            float r2 = (mv1.x != 0.f) ? __expf(s1[2] + bh1.x) : 0.f;
            float r3 = (mv1.y != 0.f) ? __expf(s1[3] + bh1.y) : 0.f;
            l_lo += p0 + p1 + r0 + r1;
            l_hi += p2 + p3 + r2 + r3;
            unsigned pa[4];
            pa[0] = packh2(p0, p1);
            pa[1] = packh2(p2, p3);
            pa[2] = packh2(r0, r1);
            pa[3] = packh2(r2, r3);
#pragma unroll
            for (int nj = 0; nj < 8; nj++) {
                unsigned bf[2];
                bf[0] = vsb[(nj * 8 + g) * KVW + t * 8 + c];
                bf[1] = vsb[(nj * 8 + g) * KVW + t * 8 + c + 4];
                mma16h(o[nj], pa, bf);
            }
        }
    }

    // epilogue -> fp16 ctx
    l_lo += __shfl_xor_sync(0xffffffffu, l_lo, 1);
    l_lo += __shfl_xor_sync(0xffffffffu, l_lo, 2);
    l_hi += __shfl_xor_sync(0xffffffffu, l_hi, 1);
    l_hi += __shfl_xor_sync(0xffffffffu, l_hi, 2);
    float inv_lo = 1.f / l_lo, inv_hi = 1.f / l_hi;
    size_t rlo = (size_t)(b * NS + qbase + wm + g) * INNERD + h * DHH;
    size_t rhi = rlo + (size_t)8 * INNERD;
#pragma unroll
    for (int nj = 0; nj < 8; nj++) {
        int dcol = nj * 8 + 2 * c;
        *(unsigned*)&g_ctxh[rlo + dcol] = packh2(o[nj][0] * inv_lo, o[nj][1] * inv_lo);
        *(unsigned*)&g_ctxh[rhi + dcol] = packh2(o[nj][2] * inv_hi, o[nj][3] * inv_hi);
    }
}

// ------------------------- launch -------------------------
extern "C" void kernel_launch(void* const* d_in, const int* in_sizes, int n_in,
                              void* d_out, int out_size) {
    const float* x         = (const float*)d_in[0];
    const float* attn_bias = (const float*)d_in[1];
    const float* ln_w      = (const float*)d_in[2];
    const float* ln_b      = (const float*)d_in[3];
    const float* wq        = (const float*)d_in[4];
    const float* wkv       = (const float*)d_in[5];
    const float* wo        = (const float*)d_in[6];
    const void*  mask      = d_in[7];

    (void)in_sizes; (void)n_in; (void)out_size;

    mask_kernel<<<1, 256>>>((const unsigned char*)mask);
    ln_kernel<<<BB * NS, 256>>>(x, ln_w, ln_b);
    transp_kernel<<<dim3(32, 32, 2), 256>>>(wq, wo);

    cudaFuncSetAttribute(gemm_h_kernel, cudaFuncAttributeMaxDynamicSharedMemorySize, GH_SMEM_BYTES);
    gemm_h_kernel<<<dim3(INNERD / 128, (BB * NS) / 128), 256, GH_SMEM_BYTES>>>(
        0, nullptr, DD, INNERD, 0.125f);

    gemm_kv_kernel<<<dim3(2, (BB * NS) / 128), 256>>>(x, wkv);

    cudaFuncSetAttribute(attn_kernel, cudaFuncAttributeMaxDynamicSharedMemorySize, ATTN_SMEM_BYTES);
    attn_kernel<<<dim3(BB * (NS / 64), HH), 128, ATTN_SMEM_BYTES>>>(attn_bias);

    gemm_h_kernel<<<dim3(DD / 128, (BB * NS) / 128), 256, GH_SMEM_BYTES>>>(
        1, (float*)d_out, INNERD, DD, 1.f);
}

// round 17
// speedup vs baseline: 1.2825x; 1.2825x over previous
#include <cuda_runtime.h>
#include <cuda_fp16.h>
#include <math.h>

#define BB 2
#define NS 2048
#define DD 1024
#define HH 16
#define DHH 64
#define INNERD 1024
#define LNEPS 1e-5f
#define NSPLIT 4
#define KT_PER_SPLIT (NS / 64 / NSPLIT)   // 8

// ------------------------- scratch -------------------------
__device__ __align__(16) __half g_xnh[BB * NS * DD];
__device__ __align__(16) __half g_qh[BB * NS * INNERD];
__device__ __align__(16) __half g_kh[BB * NS * DHH];
__device__ __align__(16) __half g_vhT[BB * DHH * NS];
__device__ __align__(16) __half g_ctxh[BB * NS * INNERD];
__device__ __align__(16) __half g_wqT[INNERD * DD];
__device__ __align__(16) __half g_woT[DD * INNERD];
__device__ __align__(16) float g_opart[NSPLIT * BB * NS * INNERD];  // 128 MB
__device__ float g_lpart[NSPLIT * HH * BB * NS];
__device__ float g_mkf[BB * NS];

// ------------------------- helpers -------------------------
__device__ __forceinline__ unsigned f2tf32(float f) {
    unsigned u; asm("cvt.rna.tf32.f32 %0, %1;" : "=r"(u) : "f"(f)); return u;
}
__device__ __forceinline__ void mma8(float* c, const unsigned* a, const unsigned* b) {
    asm volatile(
        "mma.sync.aligned.m16n8k8.row.col.f32.tf32.tf32.f32 "
        "{%0,%1,%2,%3}, {%4,%5,%6,%7}, {%8,%9}, {%0,%1,%2,%3};\n"
        : "+f"(c[0]), "+f"(c[1]), "+f"(c[2]), "+f"(c[3])
        : "r"(a[0]), "r"(a[1]), "r"(a[2]), "r"(a[3]), "r"(b[0]), "r"(b[1]));
}
__device__ __forceinline__ void mma16h(float* c, const unsigned* a, const unsigned* b) {
    asm volatile(
        "mma.sync.aligned.m16n8k16.row.col.f32.f16.f16.f32 "
        "{%0,%1,%2,%3}, {%4,%5,%6,%7}, {%8,%9}, {%0,%1,%2,%3};\n"
        : "+f"(c[0]), "+f"(c[1]), "+f"(c[2]), "+f"(c[3])
        : "r"(a[0]), "r"(a[1]), "r"(a[2]), "r"(a[3]), "r"(b[0]), "r"(b[1]));
}
__device__ __forceinline__ unsigned packh2(float lo, float hi) {
    unsigned r; asm("cvt.rn.f16x2.f32 %0, %1, %2;" : "=r"(r) : "f"(hi), "f"(lo)); return r;
}
__device__ __forceinline__ void cp16(void* dst_smem, const void* src) {
    unsigned d = (unsigned)__cvta_generic_to_shared(dst_smem);
    asm volatile("cp.async.cg.shared.global [%0], [%1], 16;\n" :: "r"(d), "l"(src));
}
__device__ __forceinline__ void cp_commit() { asm volatile("cp.async.commit_group;" ::: "memory"); }
__device__ __forceinline__ void cp_wait1() { asm volatile("cp.async.wait_group 1;" ::: "memory"); }
__device__ __forceinline__ void cp_wait0() { asm volatile("cp.async.wait_group 0;" ::: "memory"); }

// ------------------------- mask: detect dtype + expand -------------------------
__global__ void mask_kernel(const unsigned char* __restrict__ m) {
    __shared__ int cnt;
    int tid = threadIdx.x;
    if (tid == 0) cnt = 0;
    __syncthreads();
    int c = 0;
    for (int i = tid; i < 4096; i += 256) c += (m[i] != 0);
    atomicAdd(&cnt, c);
    __syncthreads();
    bool m4 = (cnt <= 2048);
    for (int i = tid; i < BB * NS; i += 256) {
        bool v = m4 ? (((const unsigned*)m)[i] != 0u) : (m[i] != 0);
        g_mkf[i] = v ? 1.f : 0.f;
    }
}

// ------------------------- LayerNorm (fp16 out) -------------------------
__global__ void ln_kernel(const float* __restrict__ x,
                          const float* __restrict__ w,
                          const float* __restrict__ b) {
    int row = blockIdx.x;
    const float* xr = x + (size_t)row * DD;
    int i4 = threadIdx.x * 4;
    float4 v = *(const float4*)&xr[i4];
    float s  = v.x + v.y + v.z + v.w;
    float s2 = v.x * v.x + v.y * v.y + v.z * v.z + v.w * v.w;
#pragma unroll
    for (int o = 16; o; o >>= 1) {
        s  += __shfl_xor_sync(0xffffffffu, s,  o);
        s2 += __shfl_xor_sync(0xffffffffu, s2, o);
    }
    __shared__ float as_[8], bs_[8];
    __shared__ float mu_s, inv_s;
    int wid = threadIdx.x >> 5, lane = threadIdx.x & 31;
    if (lane == 0) { as_[wid] = s; bs_[wid] = s2; }
    __syncthreads();
    if (threadIdx.x == 0) {
        float ts = 0.f, ts2 = 0.f;
#pragma unroll
        for (int k = 0; k < 8; k++) { ts += as_[k]; ts2 += bs_[k]; }
        float mu  = ts * (1.f / DD);
        float var = ts2 * (1.f / DD) - mu * mu;
        mu_s = mu;
        inv_s = rsqrtf(var + LNEPS);
    }
    __syncthreads();
    float mu = mu_s, inv = inv_s;
    float4 wv = *(const float4*)&w[i4];
    float4 bv = *(const float4*)&b[i4];
    float rx = (v.x - mu) * inv * wv.x + bv.x;
    float ry = (v.y - mu) * inv * wv.y + bv.y;
    float rz = (v.z - mu) * inv * wv.z + bv.z;
    float rw = (v.w - mu) * inv * wv.w + bv.w;
    __half2* d = (__half2*)&g_xnh[(size_t)row * DD + i4];
    d[0] = __floats2half2_rn(rx, ry);
    d[1] = __floats2half2_rn(rz, rw);
}

// ------------------------- weight transpose+convert -------------------------
__global__ void transp_kernel(const float* __restrict__ wq, const float* __restrict__ wo) {
    const float* in = blockIdx.z ? wo : wq;
    __half* out = blockIdx.z ? g_woT : g_wqT;
    const int R = 1024, C = 1024;
    __shared__ float t[32][33];
    int c0 = blockIdx.x * 32, r0 = blockIdx.y * 32;
    int tx = threadIdx.x & 31, ty = threadIdx.x >> 5;
#pragma unroll
    for (int i = ty; i < 32; i += 8)
        t[i][tx] = in[(size_t)(r0 + i) * C + c0 + tx];
    __syncthreads();
#pragma unroll
    for (int i = ty; i < 32; i += 8)
        out[(size_t)(c0 + i) * R + r0 + tx] = __float2half(t[tx][i]);
}

// ------------------------- tf32 kv GEMM + fused K/V^T epilogue (R14) -------------------------
#define GAS 20
#define GWS 72

__global__ __launch_bounds__(256) void gemm_kv_kernel(
        const float* __restrict__ A, const float* __restrict__ W) {
    const int K = DD, N = 2 * DHH;
    __shared__ float As[3][128 * GAS];
    __shared__ float Ws[3][16 * GWS];

    int tid = threadIdx.x, lane = tid & 31, w = tid >> 5;
    int g = lane >> 2, c = lane & 3;
    int wm = (w & 3) * 32, wn = (w >> 2) * 32;
    int bm = blockIdx.y * 128, bn = blockIdx.x * 64;
    int ar = tid >> 2, ac = (tid & 3) * 4;
    int wr = tid >> 4, wc = (tid & 15) * 4;

    const int nIter = K / 16;
    float acc[2][4][4] = {};

#pragma unroll
    for (int p = 0; p < 2; p++) {
        int k0 = p * 16;
        cp16(&As[p][ar * GAS + ac], &A[(size_t)(bm + ar) * K + k0 + ac]);
        cp16(&As[p][(ar + 64) * GAS + ac], &A[(size_t)(bm + ar + 64) * K + k0 + ac]);
        cp16(&Ws[p][wr * GWS + wc], &W[(size_t)(k0 + wr) * N + bn + wc]);
        cp_commit();
    }
    for (int i = 0; i < nIter; i++) {
        if (i == nIter - 1) cp_wait0(); else cp_wait1();
        __syncthreads();
        if (i + 2 < nIter) {
            int s = (i + 2) % 3, k0 = (i + 2) * 16;
            cp16(&As[s][ar * GAS + ac], &A[(size_t)(bm + ar) * K + k0 + ac]);
            cp16(&As[s][(ar + 64) * GAS + ac], &A[(size_t)(bm + ar + 64) * K + k0 + ac]);
            cp16(&Ws[s][wr * GWS + wc], &W[(size_t)(k0 + wr) * N + bn + wc]);
            cp_commit();
        }
        const float* as_ = As[i % 3];
        const float* ws_ = Ws[i % 3];
#pragma unroll
        for (int ks = 0; ks < 16; ks += 8) {
            unsigned af[2][4], bf[4][2];
#pragma unroll
            for (int mi = 0; mi < 2; mi++) {
                int r = wm + mi * 16 + g;
                af[mi][0] = f2tf32(as_[r * GAS + ks + c]);
                af[mi][1] = f2tf32(as_[(r + 8) * GAS + ks + c]);
                af[mi][2] = f2tf32(as_[r * GAS + ks + c + 4]);
                af[mi][3] = f2tf32(as_[(r + 8) * GAS + ks + c + 4]);
            }
#pragma unroll
            for (int ni = 0; ni < 4; ni++) {
                bf[ni][0] = f2tf32(ws_[(ks + c) * GWS + wn + ni * 8 + g]);
                bf[ni][1] = f2tf32(ws_[(ks + c + 4) * GWS + wn + ni * 8 + g]);
            }
#pragma unroll
            for (int mi = 0; mi < 2; mi++)
#pragma unroll
                for (int ni = 0; ni < 4; ni++)
                    mma8(acc[mi][ni], af[mi], bf[ni]);
        }
    }

    if (bn == 0) {
#pragma unroll
        for (int mi = 0; mi < 2; mi++)
#pragma unroll
            for (int ni = 0; ni < 4; ni++) {
                int r = bm + wm + mi * 16 + g;
                int cc = wn + ni * 8 + c * 2;
                *(unsigned*)&g_kh[(size_t)r * DHH + cc] = packh2(acc[mi][ni][0], acc[mi][ni][1]);
                *(unsigned*)&g_kh[(size_t)(r + 8) * DHH + cc] = packh2(acc[mi][ni][2], acc[mi][ni][3]);
            }
    } else {
        __syncthreads();
        __half* vt = (__half*)As;
#pragma unroll
        for (int mi = 0; mi < 2; mi++)
#pragma unroll
            for (int ni = 0; ni < 4; ni++) {
                int mr = wm + mi * 16 + g;
                int col = wn + ni * 8 + c * 2;
                *(unsigned*)&vt[mr * 72 + col] = packh2(acc[mi][ni][0], acc[mi][ni][1]);
                *(unsigned*)&vt[(mr + 8) * 72 + col] = packh2(acc[mi][ni][2], acc[mi][ni][3]);
            }
        __syncthreads();
        int d = tid >> 2, ns0 = (tid & 3) * 32;
        int bsel = bm >= NS;
        int n0 = bm - bsel * NS;
        __half tmp[32];
#pragma unroll
        for (int i = 0; i < 32; i++) tmp[i] = vt[(ns0 + i) * 72 + d];
        __half* dst = g_vhT + ((size_t)(bsel * DHH + d)) * NS + n0 + ns0;
#pragma unroll
        for (int i = 0; i < 4; i++)
            *(uint4*)(dst + i * 8) = *(uint4*)&tmp[i * 8];
    }
}

// ------------------------- fp16 GEMM 128x128 (R14) -------------------------
__device__ __forceinline__ const __half* h_a_ptr(int s) { return s == 0 ? g_xnh : g_ctxh; }
__device__ __forceinline__ const __half* h_w_ptr(int s) { return s == 0 ? g_wqT : g_woT; }

#define HST 20
#define GH_AS_WORDS (3 * 128 * HST)
#define GH_SMEM_BYTES ((2 * GH_AS_WORDS) * 4)

__global__ __launch_bounds__(256) void gemm_h_kernel(
        int sel, float* __restrict__ Cext, int K, int N, float scale) {
    const __half* A = h_a_ptr(sel);
    const __half* WT = h_w_ptr(sel);

    extern __shared__ unsigned gsm[];
    unsigned* Asb = gsm;
    unsigned* Wsb = gsm + GH_AS_WORDS;

    int tid = threadIdx.x, lane = tid & 31, w = tid >> 5;
    int g = lane >> 2, c = lane & 3;
    int wm = (w & 3) * 32, wn = (w >> 2) * 64;
    int bm = blockIdx.y * 128, bn = blockIdx.x * 128;
    int row2 = tid >> 1, seg2 = tid & 1;

    const int nIter = K / 32;
    float acc[2][8][4] = {};

    auto stage = [&](int s, int k0) {
        unsigned aw = s * (128 * HST) + row2 * HST + seg2 * 8;
        const __half* asrc = A + (size_t)(bm + row2) * K + k0 + seg2 * 16;
        cp16(&Asb[aw], asrc);
        cp16(&Asb[aw + 4], asrc + 8);
        unsigned ww = s * (128 * HST) + row2 * HST + seg2 * 8;
        const __half* wsrc = WT + (size_t)(bn + row2) * K + k0 + seg2 * 16;
        cp16(&Wsb[ww], wsrc);
        cp16(&Wsb[ww + 4], wsrc + 8);
        cp_commit();
    };

    stage(0, 0);
    stage(1, 32);

    for (int i = 0; i < nIter; i++) {
        if (i == nIter - 1) cp_wait0(); else cp_wait1();
        __syncthreads();
        if (i + 2 < nIter) stage((i + 2) % 3, (i + 2) * 32);
        const unsigned* as_ = Asb + (i % 3) * (128 * HST);
        const unsigned* ws_ = Wsb + (i % 3) * (128 * HST);
#pragma unroll
        for (int ks = 0; ks < 16; ks += 8) {
            unsigned af[2][4], bf[8][2];
#pragma unroll
            for (int mi = 0; mi < 2; mi++) {
                int r = wm + mi * 16 + g;
                af[mi][0] = as_[r * HST + ks + c];
                af[mi][1] = as_[(r + 8) * HST + ks + c];
                af[mi][2] = as_[r * HST + ks + c + 4];
                af[mi][3] = as_[(r + 8) * HST + ks + c + 4];
            }
#pragma unroll
            for (int ni = 0; ni < 8; ni++) {
                int n = wn + ni * 8 + g;
                bf[ni][0] = ws_[n * HST + ks + c];
                bf[ni][1] = ws_[n * HST + ks + c + 4];
            }
#pragma unroll
            for (int mi = 0; mi < 2; mi++)
#pragma unroll
                for (int ni = 0; ni < 8; ni++)
                    mma16h(acc[mi][ni], af[mi], bf[ni]);
        }
    }

#pragma unroll
    for (int mi = 0; mi < 2; mi++)
#pragma unroll
        for (int ni = 0; ni < 8; ni++) {
            int r = bm + wm + mi * 16 + g;
            int cc = bn + wn + ni * 8 + c * 2;
            if (sel == 0) {
                *(unsigned*)&g_qh[(size_t)r * N + cc] = packh2(acc[mi][ni][0] * scale, acc[mi][ni][1] * scale);
                *(unsigned*)&g_qh[(size_t)(r + 8) * N + cc] = packh2(acc[mi][ni][2] * scale, acc[mi][ni][3] * scale);
            } else {
                float2 r0; r0.x = acc[mi][ni][0] * scale; r0.y = acc[mi][ni][1] * scale;
                float2 r1; r1.x = acc[mi][ni][2] * scale; r1.y = acc[mi][ni][3] * scale;
                *(float2*)&Cext[(size_t)r * N + cc] = r0;
                *(float2*)&Cext[(size_t)(r + 8) * N + cc] = r1;
            }
        }
}

// ------------------------- flash attention v8: R14 config + split-K (S=4) -------------------------
// CTA = (b, h, 128 q-rows, kt-range z*8..z*8+8); per-warp code identical R14.
// Writes unnormalized O (f32) + l partials; reduce kernel combines (valid since
// softmax carries no running max -> partials are directly addable).
#define KVW 36
#define VS_OFF   (2 * 64 * KVW)
#define MK_OFF   (4 * 64 * KVW)
#define ATTN_SMEM_FLOATS (MK_OFF + 2 * 64)
#define ATTN_SMEM_BYTES  (ATTN_SMEM_FLOATS * 4)

__global__ __launch_bounds__(256, 3) void attn_kernel(const float* __restrict__ bias) {
    extern __shared__ float sm[];
    unsigned* ksu = (unsigned*)sm;
    unsigned* vsu = (unsigned*)sm + VS_OFF;

    int tid = threadIdx.x, lane = tid & 31, w = tid >> 5;
    int g = lane >> 2, c = lane & 3;
    int wm = w * 16;
    int b = blockIdx.x & 1, qt = blockIdx.x >> 1, h = blockIdx.y;
    int z = blockIdx.z;
    int qbase = qt * 128;
    int kt0 = z * KT_PER_SPLIT;

    const float* bias_r0 = bias + (size_t)h * NS * NS + (size_t)(qbase + wm + g) * NS;
    const float* bias_r8 = bias_r0 + (size_t)8 * NS;

    auto stage = [&](int kt, int buf) {
        int kbase = kt * 64;
        int r = tid >> 2, seg = tid & 3;
        unsigned* kdst = ksu + buf * (64 * KVW) + r * KVW + seg * 8;
        const __half* ksrc = g_kh + ((size_t)(b * NS + kbase + r)) * DHH + seg * 16;
        cp16(kdst, ksrc); cp16(kdst + 4, ksrc + 8);
        unsigned* vdst = vsu + buf * (64 * KVW) + r * KVW + seg * 8;
        const __half* vsrc = g_vhT + ((size_t)(b * DHH + r)) * NS + kbase + seg * 16;
        cp16(vdst, vsrc); cp16(vdst + 4, vsrc + 8);
        if (tid < 16) cp16(sm + MK_OFF + buf * 64 + tid * 4, g_mkf + b * NS + kbase + tid * 4);
        cp_commit();
    };

    stage(kt0, 0);

    const unsigned* qu = (const unsigned*)g_qh;
    unsigned qa[4][4];
    {
        size_t rlo = (size_t)(b * NS + qbase + wm + g) * 512 + h * 32;
        size_t rhi = rlo + 8 * 512;
#pragma unroll
        for (int t4 = 0; t4 < 4; t4++) {
            qa[t4][0] = qu[rlo + t4 * 8 + c];
            qa[t4][1] = qu[rhi + t4 * 8 + c];
            qa[t4][2] = qu[rlo + t4 * 8 + c + 4];
            qa[t4][3] = qu[rhi + t4 * 8 + c + 4];
        }
    }

    float o[8][4] = {};
    float l_lo = 0.f, l_hi = 0.f;

    for (int ki = 0; ki < KT_PER_SPLIT; ki++) {
        int kt = kt0 + ki;
        __syncthreads();
        if (ki + 1 < KT_PER_SPLIT) { stage(kt + 1, (ki + 1) & 1); cp_wait1(); }
        else cp_wait0();
        __syncthreads();

        int buf = ki & 1;
        int kbase = kt * 64;
        const unsigned* ksb = ksu + buf * (64 * KVW);
        const unsigned* vsb = vsu + buf * (64 * KVW);
        const float* mkb = sm + MK_OFF + buf * 64;

#pragma unroll
        for (int t = 0; t < 4; t++) {
            float2 bl0 = *(const float2*)&bias_r0[kbase + t * 16 + 2 * c];
            float2 bh0 = *(const float2*)&bias_r8[kbase + t * 16 + 2 * c];
            float2 bl1 = *(const float2*)&bias_r0[kbase + t * 16 + 8 + 2 * c];
            float2 bh1 = *(const float2*)&bias_r8[kbase + t * 16 + 8 + 2 * c];

            float s0[4] = {}, s1[4] = {};
#pragma unroll
            for (int t4 = 0; t4 < 4; t4++) {
                unsigned b0[2], b1[2];
                b0[0] = ksb[(t * 16 + g) * KVW + t4 * 8 + c];
                b0[1] = ksb[(t * 16 + g) * KVW + t4 * 8 + c + 4];
                b1[0] = ksb[(t * 16 + 8 + g) * KVW + t4 * 8 + c];
                b1[1] = ksb[(t * 16 + 8 + g) * KVW + t4 * 8 + c + 4];
                mma16h(s0, qa[t4], b0);
                mma16h(s1, qa[t4], b1);
            }
            float2 mv0 = *(const float2*)&mkb[t * 16 + 2 * c];
            float2 mv1 = *(const float2*)&mkb[t * 16 + 8 + 2 * c];
            float p0 = (mv0.x != 0.f) ? __expf(s0[0] + bl0.x) : 0.f;
            float p1 = (mv0.y != 0.f) ? __expf(s0[1] + bl0.y) : 0.f;
            float p2 = (mv0.x != 0.f) ? __expf(s0[2] + bh0.x) : 0.f;
            float p3 = (mv0.y != 0.f) ? __expf(s0[3] + bh0.y) : 0.f;
            float r0 = (mv1.x != 0.f) ? __expf(s1[0] + bl1.x) : 0.f;
            float r1 = (mv1.y != 0.f) ? __expf(s1[1] + bl1.y) : 0.f;
            float r2 = (mv1.x != 0.f) ? __expf(s1[2] + bh1.x) : 0.f;
            float r3 = (mv1.y != 0.f) ? __expf(s1[3] + bh1.y) : 0.f;
            l_lo += p0 + p1 + r0 + r1;
            l_hi += p2 + p3 + r2 + r3;
            unsigned pa[4];
            pa[0] = packh2(p0, p1);
            pa[1] = packh2(p2, p3);
            pa[2] = packh2(r0, r1);
            pa[3] = packh2(r2, r3);
#pragma unroll
            for (int nj = 0; nj < 8; nj++) {
                unsigned bf[2];
                bf[0] = vsb[(nj * 8 + g) * KVW + t * 8 + c];
                bf[1] = vsb[(nj * 8 + g) * KVW + t * 8 + c + 4];
                mma16h(o[nj], pa, bf);
            }
        }
    }

    // epilogue: write unnormalized O (f32) + l partials for this split
    l_lo += __shfl_xor_sync(0xffffffffu, l_lo, 1);
    l_lo += __shfl_xor_sync(0xffffffffu, l_lo, 2);
    l_hi += __shfl_xor_sync(0xffffffffu, l_hi, 1);
    l_hi += __shfl_xor_sync(0xffffffffu, l_hi, 2);
    int rowg_lo = b * NS + qbase + wm + g;
    if ((lane & 3) == 0) {
        float* lp = g_lpart + (size_t)z * HH * BB * NS + (size_t)h * BB * NS;
        lp[rowg_lo] = l_lo;
        lp[rowg_lo + 8] = l_hi;
    }
    float* op = g_opart + (size_t)z * BB * NS * INNERD;
    size_t rlo = (size_t)rowg_lo * INNERD + h * DHH;
    size_t rhi = rlo + (size_t)8 * INNERD;
#pragma unroll
    for (int nj = 0; nj < 8; nj++) {
        int dcol = nj * 8 + 2 * c;
        float2 w0; w0.x = o[nj][0]; w0.y = o[nj][1];
        float2 w1; w1.x = o[nj][2]; w1.y = o[nj][3];
        *(float2*)&op[rlo + dcol] = w0;
        *(float2*)&op[rhi + dcol] = w1;
    }
}

// ------------------------- split-K reduce: ctx = sum(O_s) / sum(l_s) -------------------------
__global__ __launch_bounds__(256) void attn_reduce_kernel() {
    size_t idx = ((size_t)blockIdx.x * 256 + threadIdx.x) * 4;   // element group of 4
    size_t row = idx / INNERD;
    int hd = (int)(idx % INNERD);
    int h = hd >> 6;
    float4 acc = make_float4(0.f, 0.f, 0.f, 0.f);
    float l = 0.f;
#pragma unroll
    for (int s = 0; s < NSPLIT; s++) {
        float4 v = *(const float4*)&g_opart[(size_t)s * BB * NS * INNERD + row * INNERD + hd];
        acc.x += v.x; acc.y += v.y; acc.z += v.z; acc.w += v.w;
        l += g_lpart[(size_t)s * HH * BB * NS + (size_t)h * BB * NS + row];
    }
    float inv = 1.f / l;
    __half2* dst = (__half2*)&g_ctxh[row * INNERD + hd];
    dst[0] = __floats2half2_rn(acc.x * inv, acc.y * inv);
    dst[1] = __floats2half2_rn(acc.z * inv, acc.w * inv);
}

// ------------------------- launch -------------------------
extern "C" void kernel_launch(void* const* d_in, const int* in_sizes, int n_in,
                              void* d_out, int out_size) {
    const float* x         = (const float*)d_in[0];
    const float* attn_bias = (const float*)d_in[1];
    const float* ln_w      = (const float*)d_in[2];
    const float* ln_b      = (const float*)d_in[3];
    const float* wq        = (const float*)d_in[4];
    const float* wkv       = (const float*)d_in[5];
    const float* wo        = (const float*)d_in[6];
    const void*  mask      = d_in[7];

    (void)in_sizes; (void)n_in; (void)out_size;

    mask_kernel<<<1, 256>>>((const unsigned char*)mask);
    ln_kernel<<<BB * NS, 256>>>(x, ln_w, ln_b);
    transp_kernel<<<dim3(32, 32, 2), 256>>>(wq, wo);

    cudaFuncSetAttribute(gemm_h_kernel, cudaFuncAttributeMaxDynamicSharedMemorySize, GH_SMEM_BYTES);
    gemm_h_kernel<<<dim3(INNERD / 128, (BB * NS) / 128), 256, GH_SMEM_BYTES>>>(
        0, nullptr, DD, INNERD, 0.125f);

    gemm_kv_kernel<<<dim3(2, (BB * NS) / 128), 256>>>(x, wkv);

    cudaFuncSetAttribute(attn_kernel, cudaFuncAttributeMaxDynamicSharedMemorySize, ATTN_SMEM_BYTES);
    attn_kernel<<<dim3(BB * (NS / 128), HH, NSPLIT), 256, ATTN_SMEM_BYTES>>>(attn_bias);

    attn_reduce_kernel<<<(BB * NS * INNERD / 4) / 256, 256>>>();

    gemm_h_kernel<<<dim3(DD / 128, (BB * NS) / 128), 256, GH_SMEM_BYTES>>>(
        1, (float*)d_out, INNERD, DD, 1.f);
}